// round 4
// baseline (speedup 1.0000x reference)
#include <cuda_runtime.h>
#include <math.h>
#include <stdint.h>

#define NT 365
#define NS 2048
#define NH 64
#define NG 128
#define NW 513   // NH*8+1

// ---------------- scratch (static device globals; no allocation) -------------
__device__ float4 g_flux[(NT + 4) * NS];   // [t][s] = {ps, pl*vi, pl*(1-vi), e}
__device__ float  g_tap[(NT + 4) * NS];    // [t][s] = relu(Ta)
__device__ float  g_w[(size_t)NS * NW];    // raw fc output w[s][j]
__device__ float2 g_par2[11 * NS * 32];    // [p][s][lane] = {val(h=lane), val(h=lane+32)}
__device__ float  g_vi[NS];
__device__ float  g_qb[NS];

// param slots (folded)
#define P_GM   0   // exp(w)+1
#define P_NGE  1   // -2*sigmoid(w_ge)
#define P_GL   2   // exp(w_gl)
#define P_NGL  3   // -gl
#define P_K0M  4   // 1-k0
#define P_K0GA 5   // k0*ga
#define P_NK1  6   // -k1
#define P_KKB  7   // k1*kb
#define P_KQ1  8   // k1*(1-kb)*ga
#define P_K2M  9   // 1-k2
#define P_K2GA 10  // k2*ga

__device__ __forceinline__ float sigmoidf_(float x) {
    return 1.0f / (1.0f + expf(-x));
}

// ---------------- packed f32x2 helpers (Blackwell FFMA2 path) ----------------
__device__ __forceinline__ float2 f2add(float2 a, float2 b) {
    float2 d;
    asm("{\n\t.reg .b64 a0,b0,d0;\n\t"
        "mov.b64 a0,{%2,%3};\n\tmov.b64 b0,{%4,%5};\n\t"
        "add.rn.f32x2 d0,a0,b0;\n\t"
        "mov.b64 {%0,%1},d0;\n\t}"
        : "=f"(d.x), "=f"(d.y)
        : "f"(a.x), "f"(a.y), "f"(b.x), "f"(b.y));
    return d;
}
__device__ __forceinline__ float2 f2mul(float2 a, float2 b) {
    float2 d;
    asm("{\n\t.reg .b64 a0,b0,d0;\n\t"
        "mov.b64 a0,{%2,%3};\n\tmov.b64 b0,{%4,%5};\n\t"
        "mul.rn.f32x2 d0,a0,b0;\n\t"
        "mov.b64 {%0,%1},d0;\n\t}"
        : "=f"(d.x), "=f"(d.y)
        : "f"(a.x), "f"(a.y), "f"(b.x), "f"(b.y));
    return d;
}
__device__ __forceinline__ float2 f2fma(float2 a, float2 b, float2 c) {
    float2 d;
    asm("{\n\t.reg .b64 a0,b0,c0,d0;\n\t"
        "mov.b64 a0,{%2,%3};\n\tmov.b64 b0,{%4,%5};\n\tmov.b64 c0,{%6,%7};\n\t"
        "fma.rn.f32x2 d0,a0,b0,c0;\n\t"
        "mov.b64 {%0,%1},d0;\n\t}"
        : "=f"(d.x), "=f"(d.y)
        : "f"(a.x), "f"(a.y), "f"(b.x), "f"(b.y), "f"(c.x), "f"(c.y));
    return d;
}
__device__ __forceinline__ float2 f2min(float2 a, float2 b) {
    return make_float2(fminf(a.x, b.x), fminf(a.y, b.y));
}
__device__ __forceinline__ float2 f2relu(float2 a) {
    return make_float2(fmaxf(a.x, 0.f), fmaxf(a.y, 0.f));
}
__device__ __forceinline__ float2 bc2(float s) { return make_float2(s, s); }

// ---------------- kernel A: rain/snow partition + per-site folds -------------
// runs AFTER k_params (needs g_vi)
__global__ void k_part(const float4* __restrict__ x) {
    int i = blockIdx.x * blockDim.x + threadIdx.x;
    if (i >= NT * NS) return;
    int s = i & (NS - 1);
    float4 v = x[i];
    float P = v.x, E = v.y, T1 = v.z, T2 = v.w;
    float Ta = 0.5f * (T1 + T2);
    float rP;
    if (T1 >= 0.0f)      rP = 1.0f;
    else if (T2 <= 0.0f) rP = 0.0f;
    else                 rP = 1.0f - acosf((T1 + T2) / (T2 - T1)) / 3.1415f;
    float pl = rP * P;
    float ps = (1.0f - rP) * P;
    float vi = g_vi[s];
    float plvi = pl * vi;
    g_flux[i] = make_float4(ps, plvi, pl - plvi, E);
    g_tap[i] = fmaxf(Ta, 0.0f);
}

// ---------------- kernel B: w = xc @ W^T + b ---------------------------------
__global__ void __launch_bounds__(256) k_gemm(const float* __restrict__ xc,
                                              const float4* __restrict__ W4,
                                              const float* __restrict__ b) {
    __shared__ float xs[32 * 132];
    int tid = threadIdx.x;
    int s0 = blockIdx.x << 5;
    int jbase = blockIdx.y << 6;

    for (int idx = tid; idx < 32 * NG; idx += 256) {
        int sl = idx >> 7, c = idx & (NG - 1);
        xs[sl * 132 + c] = xc[(size_t)(s0 + sl) * NG + c];
    }
    __syncthreads();

    int sl = tid & 31;
    int joff = tid >> 5;
    float acc[8] = {0.f, 0.f, 0.f, 0.f, 0.f, 0.f, 0.f, 0.f};
    const float4* wrow[8];
#pragma unroll
    for (int i = 0; i < 8; i++)
        wrow[i] = W4 + (size_t)(jbase + joff + i * 8) * (NG / 4);
    const float4* xv4 = (const float4*)&xs[sl * 132];

#pragma unroll 4
    for (int c4 = 0; c4 < NG / 4; ++c4) {
        float4 xv = xv4[c4];
#pragma unroll
        for (int i = 0; i < 8; i++) {
            float4 wv = wrow[i][c4];
            acc[i] += xv.x * wv.x + xv.y * wv.y + xv.z * wv.z + xv.w * wv.w;
        }
    }
#pragma unroll
    for (int i = 0; i < 8; i++) {
        int j = jbase + joff + i * 8;
        g_w[(size_t)(s0 + sl) * NW + j] = acc[i] + b[j];
    }
}

// ---------------- kernel C: activations + folded params ----------------------
__global__ void __launch_bounds__(64) k_params(const float* __restrict__ xc,
                                               const float* __restrict__ W,
                                               const float* __restrict__ b) {
    int wid = (blockIdx.x * blockDim.x + threadIdx.x) >> 5;
    int lane = threadIdx.x & 31;
    if (wid >= NS) return;
    int s = wid;
    const float* wr = g_w + (size_t)s * NW;

    // cooperative dot for w[s][512]
    float p = 0.f;
    const float* w512row = W + 512 * NG;
    const float* xcr = xc + (size_t)s * NG;
#pragma unroll
    for (int k = 0; k < 4; k++)
        p = fmaf(xcr[lane + 32 * k], w512row[lane + 32 * k], p);
#pragma unroll
    for (int o = 16; o; o >>= 1) p += __shfl_xor_sync(0xffffffffu, p, o);
    float w512 = p + b[512];
    float vi = sigmoidf_(w512);
    float qb = fmaxf(w512, 0.f) / (float)NH;
    if (lane == 0) { g_vi[s] = vi; g_qb[s] = qb; }

    int hA = lane, hB = lane + 32;
    float wgmA = wr[0 * NH + hA], wgmB = wr[0 * NH + hB];
    float wgeA = wr[1 * NH + hA], wgeB = wr[1 * NH + hB];
    float wk0A = wr[3 * NH + hA], wk0B = wr[3 * NH + hB];
    float wk1A = wr[4 * NH + hA], wk1B = wr[4 * NH + hB];
    float wk2A = wr[5 * NH + hA], wk2B = wr[5 * NH + hB];
    float wglA = wr[6 * NH + hA], wglB = wr[6 * NH + hB];
    float wkbA = wr[7 * NH + hA], wkbB = wr[7 * NH + hB];

    // softmax over the k1 pre-activation slice (64 values across the warp)
    float m = fmaxf(wk1A, wk1B);
#pragma unroll
    for (int o = 16; o; o >>= 1) m = fmaxf(m, __shfl_xor_sync(0xffffffffu, m, o));
    float eA = expf(wk1A - m), eB = expf(wk1B - m);
    float sum = eA + eB;
#pragma unroll
    for (int o = 16; o; o >>= 1) sum += __shfl_xor_sync(0xffffffffu, sum, o);
    float inv = 1.0f / sum;
    float gaA = eA * inv, gaB = eB * inv;

    float gmA = expf(wgmA) + 1.0f,        gmB = expf(wgmB) + 1.0f;
    float geA = 2.0f * sigmoidf_(wgeA),   geB = 2.0f * sigmoidf_(wgeB);
    float glA = expf(wglA),               glB = expf(wglB);
    float k0A = sigmoidf_(wk0A),          k0B = sigmoidf_(wk0B);
    float k1A = sigmoidf_(wk1A),          k1B = sigmoidf_(wk1B);
    float k2A = sigmoidf_(wk2A),          k2B = sigmoidf_(wk2B);
    float kbA = sigmoidf_(wkbA) / 10.0f,  kbB = sigmoidf_(wkbB) / 10.0f;

    int pb = s * 32 + lane;
#define ST(pidx, vA, vB) g_par2[(pidx) * (NS * 32) + pb] = make_float2((vA), (vB));
    ST(P_GM,   gmA,                 gmB);
    ST(P_NGE,  -geA,                -geB);
    ST(P_GL,   glA,                 glB);
    ST(P_NGL,  -glA,                -glB);
    ST(P_K0M,  1.0f - k0A,          1.0f - k0B);
    ST(P_K0GA, k0A * gaA,           k0B * gaB);
    ST(P_NK1,  -k1A,                -k1B);
    ST(P_KKB,  k1A * kbA,           k1B * kbB);
    ST(P_KQ1,  k1A * (1.0f - kbA) * gaA, k1B * (1.0f - kbB) * gaB);
    ST(P_K2M,  1.0f - k2A,          1.0f - k2B);
    ST(P_K2GA, k2A * gaA,           k2B * gaB);
#undef ST
}

// ---------------- kernel D: sequential scan ----------------------------------
// 1 warp per site; lane carries h = lane and h = lane+32 packed as f32x2.
// Reduction (full 32-lane butterfly) deferred/interleaved over 4-step unroll.
__global__ void __launch_bounds__(64) k_scan(float* __restrict__ out) {
    int lane = threadIdx.x & 31;
    int s = blockIdx.x * 2 + (threadIdx.x >> 5);
    int pb = s * 32 + lane;

#define LDP(p) g_par2[(p) * (NS * 32) + pb]
    float2 gm   = LDP(P_GM);
    float2 nge  = LDP(P_NGE);
    float2 gl   = LDP(P_GL);
    float2 ngl  = LDP(P_NGL);
    float2 k0m  = LDP(P_K0M);
    float2 k0ga = LDP(P_K0GA);
    float2 nk1  = LDP(P_NK1);
    float2 kkb  = LDP(P_KKB);
    float2 kq1  = LDP(P_KQ1);
    float2 k2m  = LDP(P_K2M);
    float2 k2ga = LDP(P_K2GA);
#undef LDP
    float qb = g_qb[s];
    const float2 neg1 = make_float2(-1.f, -1.f);

    float2 S0 = make_float2(0.f, 0.f);
    float2 H0 = ngl;
    float2 H1 = make_float2(0.f, 0.f);
    float2 H2 = make_float2(0.f, 0.f);
    float yv[4];

#define STEP(F, TP, K)                                                         \
    {                                                                          \
        float2 ps2   = bc2(F.x);                                               \
        float2 plvi2 = bc2(F.y);                                               \
        float2 plv12 = bc2(F.z);                                               \
        float2 e2    = bc2(F.w);                                               \
        float2 tap2  = bc2(TP);                                                \
        float2 am = f2mul(tap2, gm);                                           \
        float2 Sm = f2min(S0, am);                                             \
        S0 = f2fma(Sm, neg1, f2add(S0, ps2));                                  \
        float2 c1 = f2fma(e2, nge, plvi2);                                     \
        float2 G1 = f2relu(f2add(f2add(H1, Sm), c1));                          \
        float2 G0 = f2relu(f2add(f2add(H0, G1), plv12));                       \
        H0 = f2fma(G0, k0m, ngl);                                              \
        float2 y0 = f2mul(G0, k0ga);                                           \
        float2 m1 = f2min(G1, gl);                                             \
        H1 = f2min(f2fma(m1, nk1, G1), gl);                                    \
        float2 G2 = f2fma(m1, kkb, H2);                                        \
        H2 = f2mul(G2, k2m);                                                   \
        float2 y1 = f2mul(G2, k2ga);                                           \
        y0 = f2fma(m1, kq1, y0);                                               \
        yv[K] = (y0.x + y0.y) + (y1.x + y1.y);                                 \
    }

    // interleaved 32-lane butterfly over the 4 deferred y values
#define REDUCE_STORE(T, NSTEPS)                                                \
    {                                                                          \
        _Pragma("unroll")                                                      \
        for (int o = 16; o; o >>= 1) {                                         \
            float u0 = __shfl_xor_sync(0xffffffffu, yv[0], o);                 \
            float u1 = __shfl_xor_sync(0xffffffffu, yv[1], o);                 \
            float u2 = __shfl_xor_sync(0xffffffffu, yv[2], o);                 \
            float u3 = __shfl_xor_sync(0xffffffffu, yv[3], o);                 \
            yv[0] += u0; yv[1] += u1; yv[2] += u2; yv[3] += u3;                \
        }                                                                      \
        if (lane == 0) {                                                       \
            _Pragma("unroll")                                                  \
            for (int k = 0; k < (NSTEPS); ++k)                                 \
                out[(size_t)((T) + k) * NS + s] = yv[k] + qb;                  \
        }                                                                      \
    }

    // preload flux block 0 (steps 0..3); lane-uniform (broadcast) loads
    float4 fc0 = g_flux[0 * NS + s];
    float4 fc1 = g_flux[1 * NS + s];
    float4 fc2 = g_flux[2 * NS + s];
    float4 fc3 = g_flux[3 * NS + s];
    float  tp0 = g_tap[0 * NS + s];
    float  tp1 = g_tap[1 * NS + s];
    float  tp2 = g_tap[2 * NS + s];
    float  tp3 = g_tap[3 * NS + s];

    for (int tb = 0; tb < 91; ++tb) {
        int t = tb * 4;
        float4 fn0 = g_flux[(size_t)(t + 4) * NS + s];
        float4 fn1 = g_flux[(size_t)(t + 5) * NS + s];
        float4 fn2 = g_flux[(size_t)(t + 6) * NS + s];
        float4 fn3 = g_flux[(size_t)(t + 7) * NS + s];
        float  tn0 = g_tap[(size_t)(t + 4) * NS + s];
        float  tn1 = g_tap[(size_t)(t + 5) * NS + s];
        float  tn2 = g_tap[(size_t)(t + 6) * NS + s];
        float  tn3 = g_tap[(size_t)(t + 7) * NS + s];

        STEP(fc0, tp0, 0)
        STEP(fc1, tp1, 1)
        STEP(fc2, tp2, 2)
        STEP(fc3, tp3, 3)
        REDUCE_STORE(t, 4)

        fc0 = fn0; fc1 = fn1; fc2 = fn2; fc3 = fn3;
        tp0 = tn0; tp1 = tn1; tp2 = tn2; tp3 = tn3;
    }
    // epilogue: t = 364
    STEP(fc0, tp0, 0)
    REDUCE_STORE(364, 1)
#undef STEP
#undef REDUCE_STORE
}

// ---------------- launch ------------------------------------------------------
extern "C" void kernel_launch(void* const* d_in, const int* in_sizes, int n_in,
                              void* d_out, int out_size) {
    const float* x  = (const float*)d_in[0];  // [NT, NS, 4]
    const float* xc = (const float*)d_in[1];  // [NS, NG]
    const float* W  = (const float*)d_in[2];  // [NW, NG]
    const float* b  = (const float*)d_in[3];  // [NW]
    float* out = (float*)d_out;               // [NT, NS]

    dim3 gB(NS / 32, 8);
    k_gemm<<<gB, 256>>>(xc, (const float4*)W, b);
    k_params<<<NS / 2, 64>>>(xc, W, b);
    k_part<<<(NT * NS + 255) / 256, 256>>>((const float4*)x);  // needs g_vi
    k_scan<<<NS / 2, 64>>>(out);   // 1024 blocks x 2 warps; 1 site per warp
}